// round 6
// baseline (speedup 1.0000x reference)
#include <cuda_runtime.h>
#include <cuda_bf16.h>
#include <cuda_fp16.h>

#define N_CTX 4080
#define TPAD  4096
#define NS    1024
#define NH    16
#define DH    64

#define LOG2E 1.4426950408889634f
#define QSCALE (0.125f * LOG2E)

// ---------------- scratch ----------------
__device__ __nv_bfloat16 g_rb[TPAD * NS];
__device__ __nv_bfloat16 g_wt[4][NS * NS];          // [n][k]
__device__ __nv_bfloat16 g_q[NH * TPAD * DH];       // [h][t][d]  (pre-scaled by QSCALE)
__device__ __nv_bfloat16 g_k[NH * TPAD * DH];       // [h][t][d]
__device__ __half        g_vt[NH * DH * TPAD];      // [h][d][t]  fp16
__device__ __nv_bfloat16 g_att[TPAD * NS];
__device__ __nv_bfloat16 g_biasb[(size_t)TPAD * TPAD]; // bias * log2e, bf16

// ---------------- helpers ----------------
__device__ __forceinline__ void mma16816(float c[4], const unsigned a[4], const unsigned b[2]) {
    asm volatile(
        "mma.sync.aligned.m16n8k16.row.col.f32.bf16.bf16.f32 "
        "{%0,%1,%2,%3}, {%4,%5,%6,%7}, {%8,%9}, {%0,%1,%2,%3};\n"
        : "+f"(c[0]), "+f"(c[1]), "+f"(c[2]), "+f"(c[3])
        : "r"(a[0]), "r"(a[1]), "r"(a[2]), "r"(a[3]), "r"(b[0]), "r"(b[1]));
}
__device__ __forceinline__ void mma16816h(float c[4], const unsigned a[4], const unsigned b[2]) {
    asm volatile(
        "mma.sync.aligned.m16n8k16.row.col.f32.f16.f16.f32 "
        "{%0,%1,%2,%3}, {%4,%5,%6,%7}, {%8,%9}, {%0,%1,%2,%3};\n"
        : "+f"(c[0]), "+f"(c[1]), "+f"(c[2]), "+f"(c[3])
        : "r"(a[0]), "r"(a[1]), "r"(a[2]), "r"(a[3]), "r"(b[0]), "r"(b[1]));
}
__device__ __forceinline__ void ldsm4(unsigned r[4], const void* p) {
    unsigned a = (unsigned)__cvta_generic_to_shared(p);
    asm volatile("ldmatrix.sync.aligned.m8n8.x4.shared.b16 {%0,%1,%2,%3}, [%4];\n"
        : "=r"(r[0]), "=r"(r[1]), "=r"(r[2]), "=r"(r[3]) : "r"(a));
}
__device__ __forceinline__ float ex2(float x) {
    float y; asm("ex2.approx.ftz.f32 %0, %1;" : "=f"(y) : "f"(x)); return y;
}
__device__ __forceinline__ unsigned cvt_f16x2(float lo, float hi) {
    unsigned r; asm("cvt.rn.f16x2.f32 %0, %2, %1;" : "=r"(r) : "f"(lo), "f"(hi)); return r;
}
__device__ __forceinline__ unsigned ex2h2(unsigned x) {
    unsigned y; asm("ex2.approx.f16x2 %0, %1;" : "=r"(y) : "r"(x)); return y;
}
__device__ __forceinline__ void cpa16(void* dst, const void* src) {
    unsigned a = (unsigned)__cvta_generic_to_shared(dst);
    asm volatile("cp.async.cg.shared.global [%0], [%1], 16;\n" :: "r"(a), "l"(src));
}
__device__ __forceinline__ void cp_commit() { asm volatile("cp.async.commit_group;\n" ::); }
__device__ __forceinline__ void cp_wait1()  { asm volatile("cp.async.wait_group 1;\n" ::); }
__device__ __forceinline__ void cp_wait0()  { asm volatile("cp.async.wait_group 0;\n" ::); }

// ================= fused prolog: weight transpose + LN + bias conversion =================
// blocks [0,4096): transpose 4 weights; [4096,8192): layernorm rows; [8192,12288): biasconv
__global__ __launch_bounds__(256) void prolog_kernel(
    const float* __restrict__ m, const float* __restrict__ bias,
    const float* __restrict__ gamma, const float* __restrict__ beta,
    const float* __restrict__ Wq, const float* __restrict__ Wk,
    const float* __restrict__ Wv, const float* __restrict__ Wc)
{
    int b = blockIdx.x;
    int tid = threadIdx.x;

    if (b < 4096) {
        // ---- weight transpose, 32x32 tile per block ----
        __shared__ float tile[32][33];
        int w = b >> 10;
        int t = b & 1023;
        const float* W = (w == 0) ? Wq : (w == 1) ? Wk : (w == 2) ? Wv : Wc;
        int bx = (t & 31) * 32, by = (t >> 5) * 32;
        int tx = tid & 31, ty0 = tid >> 5;
        #pragma unroll
        for (int r = 0; r < 4; r++) {
            int ty = ty0 + r * 8;
            tile[ty][tx] = W[(size_t)(by + ty) * NS + bx + tx];
        }
        __syncthreads();
        #pragma unroll
        for (int r = 0; r < 4; r++) {
            int ty = ty0 + r * 8;
            g_wt[w][(size_t)(bx + ty) * NS + by + tx] = __float2bfloat16(tile[tx][ty]);
        }
        return;
    }
    if (b < 8192) {
        // ---- layernorm, one row per block ----
        int row = b - 4096;
        if (row >= N_CTX) {
            unsigned* dst = (unsigned*)(g_rb + (size_t)row * NS);
            dst[tid] = 0u; dst[tid + 256] = 0u;
            return;
        }
        float4 x = ((const float4*)(m + (size_t)row * NS))[tid];
        float s  = x.x + x.y + x.z + x.w;
        float sq = x.x * x.x + x.y * x.y + x.z * x.z + x.w * x.w;
        #pragma unroll
        for (int o = 16; o > 0; o >>= 1) {
            s  += __shfl_xor_sync(0xffffffffu, s,  o);
            sq += __shfl_xor_sync(0xffffffffu, sq, o);
        }
        __shared__ float redS[8], redQ[8], bcast[2];
        int wid = tid >> 5, ln = tid & 31;
        if (ln == 0) { redS[wid] = s; redQ[wid] = sq; }
        __syncthreads();
        if (tid == 0) {
            float S = 0.f, Q = 0.f;
            #pragma unroll
            for (int i = 0; i < 8; i++) { S += redS[i]; Q += redQ[i]; }
            float mu  = S * (1.0f / NS);
            float var = Q * (1.0f / NS) - mu * mu;
            bcast[0] = mu;
            bcast[1] = rsqrtf(var + 1e-5f);
        }
        __syncthreads();
        float mu = bcast[0], rstd = bcast[1];
        float4 g = ((const float4*)gamma)[tid];
        float4 bb = ((const float4*)beta)[tid];
        __nv_bfloat162* out = (__nv_bfloat162*)(g_rb + (size_t)row * NS);
        out[2 * tid]     = __floats2bfloat162_rn((x.x - mu) * rstd * g.x + bb.x, (x.y - mu) * rstd * g.y + bb.y);
        out[2 * tid + 1] = __floats2bfloat162_rn((x.z - mu) * rstd * g.z + bb.z, (x.w - mu) * rstd * g.w + bb.w);
        return;
    }
    // ---- bias fp32 -> bf16 * log2e, 16 floats per thread ----
    {
        size_t base = (((size_t)(b - 8192) * 256 + tid) * 16);
        #pragma unroll
        for (int r = 0; r < 4; r++) {
            float4 v = *(const float4*)(bias + base + r * 4);
            __nv_bfloat162* o = (__nv_bfloat162*)(g_biasb + base + r * 4);
            o[0] = __floats2bfloat162_rn(v.x * LOG2E, v.y * LOG2E);
            o[1] = __floats2bfloat162_rn(v.z * LOG2E, v.w * LOG2E);
        }
    }
}

// ======================= GEMM core: 128x128 tile, k-tile 64, 3-stage =======================
#define GLDS 72
#define GEMM_SMEM (3 * 2 * 128 * GLDS * 2)   // 110592 B

// ---- fused QKV GEMM ----
__global__ __launch_bounds__(256, 2) void gemm_qkv_kernel(const float* __restrict__ bq,
                                                          const float* __restrict__ bv) {
    extern __shared__ __nv_bfloat16 gsm[];

    int gn0 = blockIdx.x * 128;
    int mode = gn0 >> 10;
    int n0 = gn0 & 1023;
    int t0 = blockIdx.y * 128;
    const __nv_bfloat16* A  = g_rb;
    const __nv_bfloat16* BT = g_wt[mode];

    int tid = threadIdx.x;
    int wid = tid >> 5, lane = tid & 31, gid = lane >> 2, tig = lane & 3;
    int wm = wid & 1, wn = wid >> 1;
    int lrow = (lane & 7) + ((lane >> 3) & 1) * 8, lkhi = (lane >> 4) & 1;
    int brow = (lane & 7) + ((lane >> 4) & 1) * 8, bkhi = (lane >> 3) & 1;

    float c[4][4][4];
    #pragma unroll
    for (int i = 0; i < 4; i++)
        #pragma unroll
        for (int j = 0; j < 4; j++)
            #pragma unroll
            for (int k = 0; k < 4; k++) c[i][j][k] = 0.f;

    auto issue = [&](int kt) {
        int buf = kt % 3, k0 = kt * 64;
        __nv_bfloat16* As = gsm + buf * 2 * 128 * GLDS;
        __nv_bfloat16* Bs = As + 128 * GLDS;
        #pragma unroll
        for (int i = 0; i < 4; i++) {
            int idx = tid + i * 256;          // 0..1023
            int row = idx >> 3, cc = idx & 7;
            cpa16(&((uint4*)As)[row * 9 + cc], A  + (size_t)(t0 + row) * NS + k0 + cc * 8);
            cpa16(&((uint4*)Bs)[row * 9 + cc], BT + (size_t)(n0 + row) * NS + k0 + cc * 8);
        }
        cp_commit();
    };

    issue(0); issue(1);
    for (int kt = 0; kt < 16; kt++) {
        if (kt == 15) cp_wait0(); else cp_wait1();
        __syncthreads();
        if (kt < 14) issue(kt + 2);
        int buf = kt % 3;
        const __nv_bfloat16* As = gsm + buf * 2 * 128 * GLDS;
        const __nv_bfloat16* Bs = As + 128 * GLDS;
        #pragma unroll
        for (int ks = 0; ks < 4; ks++) {
            unsigned a[4][4], b[2][4];
            #pragma unroll
            for (int mf = 0; mf < 4; mf++)
                ldsm4(a[mf], As + (wm * 64 + mf * 16 + lrow) * GLDS + ks * 16 + lkhi * 8);
            #pragma unroll
            for (int np = 0; np < 2; np++)
                ldsm4(b[np], Bs + (wn * 32 + np * 16 + brow) * GLDS + ks * 16 + bkhi * 8);
            #pragma unroll
            for (int mf = 0; mf < 4; mf++)
                #pragma unroll
                for (int nf = 0; nf < 4; nf++)
                    mma16816(c[mf][nf], a[mf], &b[nf >> 1][(nf & 1) * 2]);
        }
    }

    #pragma unroll
    for (int mf = 0; mf < 4; mf++) {
        #pragma unroll
        for (int nf = 0; nf < 4; nf++) {
            int r0 = t0 + wm * 64 + mf * 16 + gid;
            int cn = n0 + wn * 32 + nf * 8 + tig * 2;
            float* cc = c[mf][nf];
            const float* bias = (mode == 0) ? bq : (mode == 2) ? bv : nullptr;
            float b0 = bias ? bias[cn] : 0.f;
            float b1 = bias ? bias[cn + 1] : 0.f;
            float v0 = (r0     < N_CTX) ? cc[0] + b0 : 0.f;
            float v1 = (r0     < N_CTX) ? cc[1] + b1 : 0.f;
            float v2 = (r0 + 8 < N_CTX) ? cc[2] + b0 : 0.f;
            float v3 = (r0 + 8 < N_CTX) ? cc[3] + b1 : 0.f;
            if (mode == 0) { v0 *= QSCALE; v1 *= QSCALE; v2 *= QSCALE; v3 *= QSCALE; }
            int head = cn >> 6, d = cn & 63;
            if (mode == 2) {
                __half* p0 = g_vt + ((size_t)head * DH + d) * TPAD;
                __half* p1 = p0 + TPAD;
                p0[r0]     = __float2half_rn(v0);
                p0[r0 + 8] = __float2half_rn(v2);
                p1[r0]     = __float2half_rn(v1);
                p1[r0 + 8] = __float2half_rn(v3);
            } else {
                __nv_bfloat16* base = (mode == 0 ? g_q : g_k);
                __nv_bfloat16* d0 = base + ((size_t)head * TPAD + r0) * DH + d;
                d0[0] = __float2bfloat16(v0);
                d0[1] = __float2bfloat16(v1);
                __nv_bfloat16* d1 = d0 + 8 * DH;
                d1[0] = __float2bfloat16(v2);
                d1[1] = __float2bfloat16(v3);
            }
        }
    }
}

// ---- output GEMM ----
__global__ __launch_bounds__(256, 2) void gemm_out_kernel(const float* __restrict__ bc,
                                                          const float* __restrict__ madd,
                                                          float* __restrict__ out) {
    extern __shared__ __nv_bfloat16 gsm[];

    int n0 = blockIdx.x * 128, t0 = blockIdx.y * 128;
    const __nv_bfloat16* A  = g_att;
    const __nv_bfloat16* BT = g_wt[3];

    int tid = threadIdx.x;
    int wid = tid >> 5, lane = tid & 31, gid = lane >> 2, tig = lane & 3;
    int wm = wid & 1, wn = wid >> 1;
    int lrow = (lane & 7) + ((lane >> 3) & 1) * 8, lkhi = (lane >> 4) & 1;
    int brow = (lane & 7) + ((lane >> 4) & 1) * 8, bkhi = (lane >> 3) & 1;

    float c[4][4][4];
    #pragma unroll
    for (int i = 0; i < 4; i++)
        #pragma unroll
        for (int j = 0; j < 4; j++)
            #pragma unroll
            for (int k = 0; k < 4; k++) c[i][j][k] = 0.f;

    auto issue = [&](int kt) {
        int buf = kt % 3, k0 = kt * 64;
        __nv_bfloat16* As = gsm + buf * 2 * 128 * GLDS;
        __nv_bfloat16* Bs = As + 128 * GLDS;
        #pragma unroll
        for (int i = 0; i < 4; i++) {
            int idx = tid + i * 256;
            int row = idx >> 3, cc = idx & 7;
            cpa16(&((uint4*)As)[row * 9 + cc], A  + (size_t)(t0 + row) * NS + k0 + cc * 8);
            cpa16(&((uint4*)Bs)[row * 9 + cc], BT + (size_t)(n0 + row) * NS + k0 + cc * 8);
        }
        cp_commit();
    };

    issue(0); issue(1);
    for (int kt = 0; kt < 16; kt++) {
        if (kt == 15) cp_wait0(); else cp_wait1();
        __syncthreads();
        if (kt < 14) issue(kt + 2);
        int buf = kt % 3;
        const __nv_bfloat16* As = gsm + buf * 2 * 128 * GLDS;
        const __nv_bfloat16* Bs = As + 128 * GLDS;
        #pragma unroll
        for (int ks = 0; ks < 4; ks++) {
            unsigned a[4][4], b[2][4];
            #pragma unroll
            for (int mf = 0; mf < 4; mf++)
                ldsm4(a[mf], As + (wm * 64 + mf * 16 + lrow) * GLDS + ks * 16 + lkhi * 8);
            #pragma unroll
            for (int np = 0; np < 2; np++)
                ldsm4(b[np], Bs + (wn * 32 + np * 16 + brow) * GLDS + ks * 16 + bkhi * 8);
            #pragma unroll
            for (int mf = 0; mf < 4; mf++)
                #pragma unroll
                for (int nf = 0; nf < 4; nf++)
                    mma16816(c[mf][nf], a[mf], &b[nf >> 1][(nf & 1) * 2]);
        }
    }

    #pragma unroll
    for (int mf = 0; mf < 4; mf++) {
        #pragma unroll
        for (int nf = 0; nf < 4; nf++) {
            int r0 = t0 + wm * 64 + mf * 16 + gid;
            int cn = n0 + wn * 32 + nf * 8 + tig * 2;
            float* cc = c[mf][nf];
            if (r0 < N_CTX) {
                out[(size_t)r0 * NS + cn]     = madd[(size_t)r0 * NS + cn]     + cc[0] + bc[cn];
                out[(size_t)r0 * NS + cn + 1] = madd[(size_t)r0 * NS + cn + 1] + cc[1] + bc[cn + 1];
            }
            if (r0 + 8 < N_CTX) {
                out[(size_t)(r0 + 8) * NS + cn]     = madd[(size_t)(r0 + 8) * NS + cn]     + cc[2] + bc[cn];
                out[(size_t)(r0 + 8) * NS + cn + 1] = madd[(size_t)(r0 + 8) * NS + cn + 1] + cc[3] + bc[cn + 1];
            }
        }
    }
}

// ======================= flash attention: 128 q x 64 k, 3-stage, 2 CTAs/SM =======================
#define LPK 72
#define ATTN_SMEM ((128 * LPK + 3 * 64 * LPK + 3 * 64 * LPK) * 2)   // 73728 B

__global__ __launch_bounds__(256, 2) void attn_kernel() {
    extern __shared__ char smraw[];
    __nv_bfloat16* Qs = (__nv_bfloat16*)smraw;            // 128*LPK
    __nv_bfloat16* Ks = Qs + 128 * LPK;                   // 3 * 64*LPK
    __half*        Vt = (__half*)(Ks + 3 * 64 * LPK);     // 3 * 64*LPK

    int head = blockIdx.x;
    int q0   = blockIdx.y * 128;
    int tid = threadIdx.x, wid = tid >> 5, lane = tid & 31, gid = lane >> 2, tig = lane & 3;
    int lrow = (lane & 7) + ((lane >> 3) & 1) * 8, lkhi = (lane >> 4) & 1;
    int brow = (lane & 7) + ((lane >> 4) & 1) * 8, bkhi = (lane >> 3) & 1;

    const __nv_bfloat16* gq = g_q  + (size_t)head * TPAD * DH;
    const __nv_bfloat16* gk = g_k  + (size_t)head * TPAD * DH;
    const __half*        gv = g_vt + (size_t)head * DH * TPAD;

    auto issue = [&](int kt) {
        int buf = kt % 3, k0 = kt * 64;
        __nv_bfloat16* kd = Ks + buf * 64 * LPK;
        __half*        vd = Vt + buf * 64 * LPK;
        #pragma unroll
        for (int i = 0; i < 2; i++) {
            int idx = tid + i * 256;
            int row = idx >> 3, cc = idx & 7;
            cpa16(&((uint4*)kd)[row * 9 + cc], gk + (size_t)(k0 + row) * DH + cc * 8);
        }
        #pragma unroll
        for (int i = 0; i < 2; i++) {
            int idx = tid + i * 256;
            int row = idx >> 3, cc = idx & 7;
            cpa16(&((uint4*)vd)[row * 9 + cc], gv + (size_t)row * TPAD + k0 + cc * 8);
        }
        cp_commit();
    };

    issue(0); issue(1);
    #pragma unroll
    for (int i = 0; i < 4; i++) {
        int idx = tid + i * 256;
        int row = idx >> 3, cc = idx & 7;
        ((uint4*)Qs)[row * 9 + cc] = *(const uint4*)(gq + (size_t)(q0 + row) * DH + cc * 8);
    }
    __syncthreads();

    unsigned qa[4][4];
    #pragma unroll
    for (int ks = 0; ks < 4; ks++)
        ldsm4(qa[ks], Qs + (wid * 16 + lrow) * LPK + ks * 16 + lkhi * 8);

    float oacc[8][4], oacc_l[4];
    #pragma unroll
    for (int j = 0; j < 8; j++)
        #pragma unroll
        for (int i = 0; i < 4; i++) oacc[j][i] = 0.f;
    #pragma unroll
    for (int i = 0; i < 4; i++) oacc_l[i] = 0.f;

    float mr0 = -1e30f, mr1 = -1e30f;
    int qrow = q0 + wid * 16 + gid;
    const __nv_bfloat16* bptr0 = g_biasb + (size_t)qrow * TPAD + tig * 2;
    const __nv_bfloat16* bptr1 = bptr0 + 8 * TPAD;

    const unsigned b_ones[2] = {0x3C003C00u, 0x3C003C00u};   // fp16 (1,1)

    // bias registers for tile 0 (double-buffered across iterations)
    unsigned bb0[8], bb1[8];
    #pragma unroll
    for (int j = 0; j < 8; j++) {
        bb0[j] = *(const unsigned*)(bptr0 + j * 8);
        bb1[j] = *(const unsigned*)(bptr1 + j * 8);
    }

    for (int kt = 0; kt < 64; kt++) {
        // S c-fragments initialized from prefetched bias registers
        float s[8][4];
        #pragma unroll
        for (int j = 0; j < 8; j++) {
            s[j][0] = __uint_as_float(bb0[j] << 16);
            s[j][1] = __uint_as_float(bb0[j] & 0xffff0000u);
            s[j][2] = __uint_as_float(bb1[j] << 16);
            s[j][3] = __uint_as_float(bb1[j] & 0xffff0000u);
        }

        if (kt == 63) cp_wait0(); else cp_wait1();
        __syncthreads();
        if (kt < 62) issue(kt + 2);
        int buf = kt % 3;
        const __nv_bfloat16* kd = Ks + buf * 64 * LPK;
        const __half*        vd = Vt + buf * 64 * LPK;

        // S += Q K^T (log2-domain: q pre-scaled, bias pre-scaled)
        #pragma unroll
        for (int ks = 0; ks < 4; ks++) {
            #pragma unroll
            for (int jp = 0; jp < 4; jp++) {
                unsigned kb[4];
                ldsm4(kb, kd + (jp * 16 + brow) * LPK + ks * 16 + bkhi * 8);
                mma16816(s[2 * jp],     qa[ks], &kb[0]);
                mma16816(s[2 * jp + 1], qa[ks], &kb[2]);
            }
        }

        // prefetch next iteration's bias (bb regs dead once s is initialized)
        if (kt < 63) {
            int k0n = (kt + 1) * 64;
            #pragma unroll
            for (int j = 0; j < 8; j++) {
                bb0[j] = *(const unsigned*)(bptr0 + k0n + j * 8);
                bb1[j] = *(const unsigned*)(bptr1 + k0n + j * 8);
            }
        }

        // row max
        float rm0 = -1e30f, rm1 = -1e30f;
        #pragma unroll
        for (int j = 0; j < 8; j++) {
            rm0 = fmaxf(rm0, fmaxf(s[j][0], s[j][1]));
            rm1 = fmaxf(rm1, fmaxf(s[j][2], s[j][3]));
        }
        rm0 = fmaxf(rm0, __shfl_xor_sync(0xffffffffu, rm0, 1));
        rm0 = fmaxf(rm0, __shfl_xor_sync(0xffffffffu, rm0, 2));
        rm1 = fmaxf(rm1, __shfl_xor_sync(0xffffffffu, rm1, 1));
        rm1 = fmaxf(rm1, __shfl_xor_sync(0xffffffffu, rm1, 2));
        float mn0 = fmaxf(mr0, rm0), mn1 = fmaxf(mr1, rm1);

        // p = 2^(s - mn), packed fp16
        unsigned ph0[8], ph1[8];
        #pragma unroll
        for (int j = 0; j < 8; j++) {
            ph0[j] = ex2h2(cvt_f16x2(s[j][0] - mn0, s[j][1] - mn0));
            ph1[j] = ex2h2(cvt_f16x2(s[j][2] - mn1, s[j][3] - mn1));
        }

        // rescale O and l if any row in the warp got a new max
        if (__any_sync(0xffffffffu, (mn0 > mr0) | (mn1 > mr1))) {
            float al0 = ex2(mr0 - mn0), al1 = ex2(mr1 - mn1);
            #pragma unroll
            for (int j = 0; j < 8; j++) {
                oacc[j][0] *= al0; oacc[j][1] *= al0;
                oacc[j][2] *= al1; oacc[j][3] *= al1;
            }
            oacc_l[0] *= al0; oacc_l[1] *= al0;
            oacc_l[2] *= al1; oacc_l[3] *= al1;
        }
        mr0 = mn0; mr1 = mn1;

        // O += P V (fp16); l via all-ones B fragment
        #pragma unroll
        for (int kk = 0; kk < 4; kk++) {
            unsigned a[4];
            a[0] = ph0[2 * kk];
            a[1] = ph1[2 * kk];
            a[2] = ph0[2 * kk + 1];
            a[3] = ph1[2 * kk + 1];
            #pragma unroll
            for (int jp = 0; jp < 4; jp++) {
                unsigned vb[4];
                ldsm4(vb, vd + (jp * 16 + brow) * LPK + kk * 16 + bkhi * 8);
                mma16816h(oacc[2 * jp],     a, &vb[0]);
                mma16816h(oacc[2 * jp + 1], a, &vb[2]);
            }
            mma16816h(oacc_l, a, b_ones);
        }
    }

    float inv0 = 1.f / oacc_l[0], inv1 = 1.f / oacc_l[2];
    #pragma unroll
    for (int j = 0; j < 8; j++) {
        int col = head * DH + j * 8 + tig * 2;
        __nv_bfloat16* d0 = g_att + (size_t)qrow * NS + col;
        __nv_bfloat16* d1 = g_att + (size_t)(qrow + 8) * NS + col;
        d0[0] = __float2bfloat16(oacc[j][0] * inv0);
        d0[1] = __float2bfloat16(oacc[j][1] * inv0);
        d1[0] = __float2bfloat16(oacc[j][2] * inv1);
        d1[1] = __float2bfloat16(oacc[j][3] * inv1);
    }
}

// ---------------- launch ----------------
extern "C" void kernel_launch(void* const* d_in, const int* in_sizes, int n_in,
                              void* d_out, int out_size) {
    const float* m     = (const float*)d_in[0];
    const float* bias  = (const float*)d_in[1];
    const float* gamma = (const float*)d_in[2];
    const float* beta  = (const float*)d_in[3];
    const float* Wq    = (const float*)d_in[4];
    const float* bq    = (const float*)d_in[5];
    const float* Wk    = (const float*)d_in[6];
    const float* Wv    = (const float*)d_in[7];
    const float* bv    = (const float*)d_in[8];
    const float* Wc    = (const float*)d_in[9];
    const float* bc    = (const float*)d_in[10];
    float* out = (float*)d_out;

    prolog_kernel<<<12288, 256>>>(m, bias, gamma, beta, Wq, Wk, Wv, Wc);

    cudaFuncSetAttribute(gemm_qkv_kernel, cudaFuncAttributeMaxDynamicSharedMemorySize, GEMM_SMEM);
    gemm_qkv_kernel<<<dim3(24, 32), 256, GEMM_SMEM>>>(bq, bv);

    cudaFuncSetAttribute(attn_kernel, cudaFuncAttributeMaxDynamicSharedMemorySize, ATTN_SMEM);
    attn_kernel<<<dim3(NH, TPAD / 128), 256, ATTN_SMEM>>>();

    cudaFuncSetAttribute(gemm_out_kernel, cudaFuncAttributeMaxDynamicSharedMemorySize, GEMM_SMEM);
    gemm_out_kernel<<<dim3(8, 32), 256, GEMM_SMEM>>>(bc, m, out);
}

// round 8
// speedup vs baseline: 1.0616x; 1.0616x over previous
#include <cuda_runtime.h>
#include <cuda_bf16.h>
#include <cuda_fp16.h>

#define N_CTX 4080
#define TPAD  4096
#define NS    1024
#define NH    16
#define DH    64

#define LOG2E 1.4426950408889634f
#define QSCALE (0.125f * LOG2E)

// ---------------- scratch ----------------
__device__ __nv_bfloat16 g_rb[TPAD * NS];
__device__ __nv_bfloat16 g_wt[4][NS * NS];          // [n][k]
__device__ __nv_bfloat16 g_q[NH * TPAD * DH];       // [h][t][d]  (pre-scaled by QSCALE)
__device__ __nv_bfloat16 g_k[NH * TPAD * DH];       // [h][t][d]
__device__ __half        g_vt[NH * DH * TPAD];      // [h][d][t]  fp16
__device__ __nv_bfloat16 g_att[TPAD * NS];
__device__ __nv_bfloat16 g_biasb[(size_t)TPAD * TPAD]; // bias * log2e, bf16

// ---------------- helpers ----------------
__device__ __forceinline__ void mma16816(float c[4], const unsigned a[4], const unsigned b[2]) {
    asm volatile(
        "mma.sync.aligned.m16n8k16.row.col.f32.bf16.bf16.f32 "
        "{%0,%1,%2,%3}, {%4,%5,%6,%7}, {%8,%9}, {%0,%1,%2,%3};\n"
        : "+f"(c[0]), "+f"(c[1]), "+f"(c[2]), "+f"(c[3])
        : "r"(a[0]), "r"(a[1]), "r"(a[2]), "r"(a[3]), "r"(b[0]), "r"(b[1]));
}
__device__ __forceinline__ void mma16816h(float c[4], const unsigned a[4], const unsigned b[2]) {
    asm volatile(
        "mma.sync.aligned.m16n8k16.row.col.f32.f16.f16.f32 "
        "{%0,%1,%2,%3}, {%4,%5,%6,%7}, {%8,%9}, {%0,%1,%2,%3};\n"
        : "+f"(c[0]), "+f"(c[1]), "+f"(c[2]), "+f"(c[3])
        : "r"(a[0]), "r"(a[1]), "r"(a[2]), "r"(a[3]), "r"(b[0]), "r"(b[1]));
}
__device__ __forceinline__ void ldsm4(unsigned r[4], const void* p) {
    unsigned a = (unsigned)__cvta_generic_to_shared(p);
    asm volatile("ldmatrix.sync.aligned.m8n8.x4.shared.b16 {%0,%1,%2,%3}, [%4];\n"
        : "=r"(r[0]), "=r"(r[1]), "=r"(r[2]), "=r"(r[3]) : "r"(a));
}
__device__ __forceinline__ float ex2(float x) {
    float y; asm("ex2.approx.ftz.f32 %0, %1;" : "=f"(y) : "f"(x)); return y;
}
__device__ __forceinline__ unsigned cvt_f16x2(float lo, float hi) {
    unsigned r; asm("cvt.rn.f16x2.f32 %0, %2, %1;" : "=r"(r) : "f"(lo), "f"(hi)); return r;
}
__device__ __forceinline__ unsigned ex2h2(unsigned x) {
    unsigned y; asm("ex2.approx.f16x2 %0, %1;" : "=r"(y) : "r"(x)); return y;
}
__device__ __forceinline__ void cpa16(void* dst, const void* src) {
    unsigned a = (unsigned)__cvta_generic_to_shared(dst);
    asm volatile("cp.async.cg.shared.global [%0], [%1], 16;\n" :: "r"(a), "l"(src));
}
__device__ __forceinline__ void cp_commit() { asm volatile("cp.async.commit_group;\n" ::); }
__device__ __forceinline__ void cp_wait1()  { asm volatile("cp.async.wait_group 1;\n" ::); }
__device__ __forceinline__ void cp_wait0()  { asm volatile("cp.async.wait_group 0;\n" ::); }

// ================= fused prolog: weight transpose + LN =================
// blocks [0,4096): transpose 4 weights; [4096,8192): layernorm rows
__global__ __launch_bounds__(256) void prolog_kernel(
    const float* __restrict__ m,
    const float* __restrict__ gamma, const float* __restrict__ beta,
    const float* __restrict__ Wq, const float* __restrict__ Wk,
    const float* __restrict__ Wv, const float* __restrict__ Wc)
{
    int b = blockIdx.x;
    int tid = threadIdx.x;

    if (b < 4096) {
        __shared__ float tile[32][33];
        int w = b >> 10;
        int t = b & 1023;
        const float* W = (w == 0) ? Wq : (w == 1) ? Wk : (w == 2) ? Wv : Wc;
        int bx = (t & 31) * 32, by = (t >> 5) * 32;
        int tx = tid & 31, ty0 = tid >> 5;
        #pragma unroll
        for (int r = 0; r < 4; r++) {
            int ty = ty0 + r * 8;
            tile[ty][tx] = W[(size_t)(by + ty) * NS + bx + tx];
        }
        __syncthreads();
        #pragma unroll
        for (int r = 0; r < 4; r++) {
            int ty = ty0 + r * 8;
            g_wt[w][(size_t)(bx + ty) * NS + by + tx] = __float2bfloat16(tile[tx][ty]);
        }
        return;
    }
    // ---- layernorm, one row per block ----
    int row = b - 4096;
    if (row >= N_CTX) {
        unsigned* dst = (unsigned*)(g_rb + (size_t)row * NS);
        dst[tid] = 0u; dst[tid + 256] = 0u;
        return;
    }
    float4 x = ((const float4*)(m + (size_t)row * NS))[tid];
    float s  = x.x + x.y + x.z + x.w;
    float sq = x.x * x.x + x.y * x.y + x.z * x.z + x.w * x.w;
    #pragma unroll
    for (int o = 16; o > 0; o >>= 1) {
        s  += __shfl_xor_sync(0xffffffffu, s,  o);
        sq += __shfl_xor_sync(0xffffffffu, sq, o);
    }
    __shared__ float redS[8], redQ[8], bcast[2];
    int wid = tid >> 5, ln = tid & 31;
    if (ln == 0) { redS[wid] = s; redQ[wid] = sq; }
    __syncthreads();
    if (tid == 0) {
        float S = 0.f, Q = 0.f;
        #pragma unroll
        for (int i = 0; i < 8; i++) { S += redS[i]; Q += redQ[i]; }
        float mu  = S * (1.0f / NS);
        float var = Q * (1.0f / NS) - mu * mu;
        bcast[0] = mu;
        bcast[1] = rsqrtf(var + 1e-5f);
    }
    __syncthreads();
    float mu = bcast[0], rstd = bcast[1];
    float4 g = ((const float4*)gamma)[tid];
    float4 bb = ((const float4*)beta)[tid];
    __nv_bfloat162* out = (__nv_bfloat162*)(g_rb + (size_t)row * NS);
    out[2 * tid]     = __floats2bfloat162_rn((x.x - mu) * rstd * g.x + bb.x, (x.y - mu) * rstd * g.y + bb.y);
    out[2 * tid + 1] = __floats2bfloat162_rn((x.z - mu) * rstd * g.z + bb.z, (x.w - mu) * rstd * g.w + bb.w);
}

// ======================= fused QKV GEMM (3-stage, ldmatrix, k32) + biasconv tail =======================
// grid (32, 32): bx<24 -> gemm tile (mode = gn0>>10), bx>=24 -> bias conversion chunk
__global__ __launch_bounds__(256, 2) void gemm_qkv_kernel(const float* __restrict__ bq,
                                                          const float* __restrict__ bv,
                                                          const float* __restrict__ bias) {
    constexpr int LDS_ = 40;  // 32 + 8 pad
    __shared__ __nv_bfloat16 As[3][128 * LDS_];
    __shared__ __nv_bfloat16 Bs[3][128 * LDS_];

    int tid = threadIdx.x;

    if (blockIdx.x >= 24) {
        // ---- bias fp32 -> bf16 * log2e; 256 chunks of 65536 elements ----
        int chunk = (blockIdx.x - 24) * 32 + blockIdx.y;
        size_t base = (size_t)chunk * 65536 + tid * 4;
        #pragma unroll 4
        for (int it = 0; it < 64; it++) {
            float4 v = *(const float4*)(bias + base);
            __nv_bfloat162* o = (__nv_bfloat162*)(g_biasb + base);
            o[0] = __floats2bfloat162_rn(v.x * LOG2E, v.y * LOG2E);
            o[1] = __floats2bfloat162_rn(v.z * LOG2E, v.w * LOG2E);
            base += 1024;
        }
        return;
    }

    int gn0 = blockIdx.x * 128;
    int mode = gn0 >> 10;
    int n0 = gn0 & 1023;
    int t0 = blockIdx.y * 128;
    const __nv_bfloat16* A  = g_rb;
    const __nv_bfloat16* BT = g_wt[mode];

    int wid = tid >> 5, lane = tid & 31, gid = lane >> 2, tig = lane & 3;
    int wm = wid & 1, wn = wid >> 1;
    int lrow = (lane & 7) + ((lane >> 3) & 1) * 8, lkhi = (lane >> 4) & 1;
    int brow = (lane & 7) + ((lane >> 4) & 1) * 8, bkhi = (lane >> 3) & 1;

    float c[4][4][4];
    #pragma unroll
    for (int i = 0; i < 4; i++)
        #pragma unroll
        for (int j = 0; j < 4; j++)
            #pragma unroll
            for (int k = 0; k < 4; k++) c[i][j][k] = 0.f;

    auto issue = [&](int kt) {
        int buf = kt % 3, k0 = kt * 32;
        #pragma unroll
        for (int i = 0; i < 2; i++) {
            int idx = tid + i * 256;
            int row = idx >> 2, cc = idx & 3;
            cpa16(&((uint4*)As[buf])[row * 5 + cc], A  + (size_t)(t0 + row) * NS + k0 + cc * 8);
            cpa16(&((uint4*)Bs[buf])[row * 5 + cc], BT + (size_t)(n0 + row) * NS + k0 + cc * 8);
        }
        cp_commit();
    };

    issue(0); issue(1);
    for (int kt = 0; kt < 32; kt++) {
        if (kt == 31) cp_wait0(); else cp_wait1();
        __syncthreads();
        if (kt < 30) issue(kt + 2);
        int buf = kt % 3;
        #pragma unroll
        for (int ks = 0; ks < 2; ks++) {
            unsigned a[4][4], b[2][4];
            #pragma unroll
            for (int mf = 0; mf < 4; mf++)
                ldsm4(a[mf], As[buf] + (wm * 64 + mf * 16 + lrow) * LDS_ + ks * 16 + lkhi * 8);
            #pragma unroll
            for (int np = 0; np < 2; np++)
                ldsm4(b[np], Bs[buf] + (wn * 32 + np * 16 + brow) * LDS_ + ks * 16 + bkhi * 8);
            #pragma unroll
            for (int mf = 0; mf < 4; mf++)
                #pragma unroll
                for (int nf = 0; nf < 4; nf++)
                    mma16816(c[mf][nf], a[mf], &b[nf >> 1][(nf & 1) * 2]);
        }
    }

    #pragma unroll
    for (int mf = 0; mf < 4; mf++) {
        #pragma unroll
        for (int nf = 0; nf < 4; nf++) {
            int r0 = t0 + wm * 64 + mf * 16 + gid;
            int cn = n0 + wn * 32 + nf * 8 + tig * 2;
            float* cc = c[mf][nf];
            const float* bias2 = (mode == 0) ? bq : (mode == 2) ? bv : nullptr;
            float b0 = bias2 ? bias2[cn] : 0.f;
            float b1 = bias2 ? bias2[cn + 1] : 0.f;
            float v0 = (r0     < N_CTX) ? cc[0] + b0 : 0.f;
            float v1 = (r0     < N_CTX) ? cc[1] + b1 : 0.f;
            float v2 = (r0 + 8 < N_CTX) ? cc[2] + b0 : 0.f;
            float v3 = (r0 + 8 < N_CTX) ? cc[3] + b1 : 0.f;
            if (mode == 0) { v0 *= QSCALE; v1 *= QSCALE; v2 *= QSCALE; v3 *= QSCALE; }
            int head = cn >> 6, d = cn & 63;
            if (mode == 2) {
                __half* p0 = g_vt + ((size_t)head * DH + d) * TPAD;
                __half* p1 = p0 + TPAD;
                p0[r0]     = __float2half_rn(v0);
                p0[r0 + 8] = __float2half_rn(v2);
                p1[r0]     = __float2half_rn(v1);
                p1[r0 + 8] = __float2half_rn(v3);
            } else {
                __nv_bfloat16* base = (mode == 0 ? g_q : g_k);
                __nv_bfloat16* d0 = base + ((size_t)head * TPAD + r0) * DH + d;
                d0[0] = __float2bfloat16(v0);
                d0[1] = __float2bfloat16(v1);
                __nv_bfloat16* d1 = d0 + 8 * DH;
                d1[0] = __float2bfloat16(v2);
                d1[1] = __float2bfloat16(v3);
            }
        }
    }
}

// ======================= output GEMM (3-stage, ldmatrix, k32) =======================
__global__ __launch_bounds__(256, 2) void gemm_out_kernel(const float* __restrict__ bc,
                                                          const float* __restrict__ madd,
                                                          float* __restrict__ out) {
    constexpr int LDS_ = 40;
    __shared__ __nv_bfloat16 As[3][128 * LDS_];
    __shared__ __nv_bfloat16 Bs[3][128 * LDS_];

    int n0 = blockIdx.x * 128, t0 = blockIdx.y * 128;
    const __nv_bfloat16* A  = g_att;
    const __nv_bfloat16* BT = g_wt[3];

    int tid = threadIdx.x;
    int wid = tid >> 5, lane = tid & 31, gid = lane >> 2, tig = lane & 3;
    int wm = wid & 1, wn = wid >> 1;
    int lrow = (lane & 7) + ((lane >> 3) & 1) * 8, lkhi = (lane >> 4) & 1;
    int brow = (lane & 7) + ((lane >> 4) & 1) * 8, bkhi = (lane >> 3) & 1;

    float c[4][4][4];
    #pragma unroll
    for (int i = 0; i < 4; i++)
        #pragma unroll
        for (int j = 0; j < 4; j++)
            #pragma unroll
            for (int k = 0; k < 4; k++) c[i][j][k] = 0.f;

    auto issue = [&](int kt) {
        int buf = kt % 3, k0 = kt * 32;
        #pragma unroll
        for (int i = 0; i < 2; i++) {
            int idx = tid + i * 256;
            int row = idx >> 2, cc = idx & 3;
            cpa16(&((uint4*)As[buf])[row * 5 + cc], A  + (size_t)(t0 + row) * NS + k0 + cc * 8);
            cpa16(&((uint4*)Bs[buf])[row * 5 + cc], BT + (size_t)(n0 + row) * NS + k0 + cc * 8);
        }
        cp_commit();
    };

    issue(0); issue(1);
    for (int kt = 0; kt < 32; kt++) {
        if (kt == 31) cp_wait0(); else cp_wait1();
        __syncthreads();
        if (kt < 30) issue(kt + 2);
        int buf = kt % 3;
        #pragma unroll
        for (int ks = 0; ks < 2; ks++) {
            unsigned a[4][4], b[2][4];
            #pragma unroll
            for (int mf = 0; mf < 4; mf++)
                ldsm4(a[mf], As[buf] + (wm * 64 + mf * 16 + lrow) * LDS_ + ks * 16 + lkhi * 8);
            #pragma unroll
            for (int np = 0; np < 2; np++)
                ldsm4(b[np], Bs[buf] + (wn * 32 + np * 16 + brow) * LDS_ + ks * 16 + bkhi * 8);
            #pragma unroll
            for (int mf = 0; mf < 4; mf++)
                #pragma unroll
                for (int nf = 0; nf < 4; nf++)
                    mma16816(c[mf][nf], a[mf], &b[nf >> 1][(nf & 1) * 2]);
        }
    }

    #pragma unroll
    for (int mf = 0; mf < 4; mf++) {
        #pragma unroll
        for (int nf = 0; nf < 4; nf++) {
            int r0 = t0 + wm * 64 + mf * 16 + gid;
            int cn = n0 + wn * 32 + nf * 8 + tig * 2;
            float* cc = c[mf][nf];
            if (r0 < N_CTX) {
                out[(size_t)r0 * NS + cn]     = madd[(size_t)r0 * NS + cn]     + cc[0] + bc[cn];
                out[(size_t)r0 * NS + cn + 1] = madd[(size_t)r0 * NS + cn + 1] + cc[1] + bc[cn + 1];
            }
            if (r0 + 8 < N_CTX) {
                out[(size_t)(r0 + 8) * NS + cn]     = madd[(size_t)(r0 + 8) * NS + cn]     + cc[2] + bc[cn];
                out[(size_t)(r0 + 8) * NS + cn + 1] = madd[(size_t)(r0 + 8) * NS + cn + 1] + cc[3] + bc[cn + 1];
            }
        }
    }
}

// ======================= flash attention: 128 q x 64 k, 3-stage, 2 CTAs/SM (round-5 exact) =======================
#define LPK 72
#define ATTN_SMEM ((128 * LPK + 3 * 64 * LPK + 3 * 64 * LPK) * 2)   // 73728 B

__global__ __launch_bounds__(256, 2) void attn_kernel() {
    extern __shared__ char smraw[];
    __nv_bfloat16* Qs = (__nv_bfloat16*)smraw;            // 128*LPK
    __nv_bfloat16* Ks = Qs + 128 * LPK;                   // 3 * 64*LPK
    __half*        Vt = (__half*)(Ks + 3 * 64 * LPK);     // 3 * 64*LPK

    int head = blockIdx.x;
    int q0   = blockIdx.y * 128;
    int tid = threadIdx.x, wid = tid >> 5, lane = tid & 31, gid = lane >> 2, tig = lane & 3;
    int lrow = (lane & 7) + ((lane >> 3) & 1) * 8, lkhi = (lane >> 4) & 1;
    int brow = (lane & 7) + ((lane >> 4) & 1) * 8, bkhi = (lane >> 3) & 1;

    const __nv_bfloat16* gq = g_q  + (size_t)head * TPAD * DH;
    const __nv_bfloat16* gk = g_k  + (size_t)head * TPAD * DH;
    const __half*        gv = g_vt + (size_t)head * DH * TPAD;

    auto issue = [&](int kt) {
        int buf = kt % 3, k0 = kt * 64;
        __nv_bfloat16* kd = Ks + buf * 64 * LPK;
        __half*        vd = Vt + buf * 64 * LPK;
        #pragma unroll
        for (int i = 0; i < 2; i++) {
            int idx = tid + i * 256;
            int row = idx >> 3, cc = idx & 7;
            cpa16(&((uint4*)kd)[row * 9 + cc], gk + (size_t)(k0 + row) * DH + cc * 8);
        }
        #pragma unroll
        for (int i = 0; i < 2; i++) {
            int idx = tid + i * 256;
            int row = idx >> 3, cc = idx & 7;
            cpa16(&((uint4*)vd)[row * 9 + cc], gv + (size_t)row * TPAD + k0 + cc * 8);
        }
        cp_commit();
    };

    issue(0); issue(1);
    #pragma unroll
    for (int i = 0; i < 4; i++) {
        int idx = tid + i * 256;
        int row = idx >> 3, cc = idx & 7;
        ((uint4*)Qs)[row * 9 + cc] = *(const uint4*)(gq + (size_t)(q0 + row) * DH + cc * 8);
    }
    __syncthreads();

    unsigned qa[4][4];
    #pragma unroll
    for (int ks = 0; ks < 4; ks++)
        ldsm4(qa[ks], Qs + (wid * 16 + lrow) * LPK + ks * 16 + lkhi * 8);

    float oacc[8][4], oacc_l[4];
    #pragma unroll
    for (int j = 0; j < 8; j++)
        #pragma unroll
        for (int i = 0; i < 4; i++) oacc[j][i] = 0.f;
    #pragma unroll
    for (int i = 0; i < 4; i++) oacc_l[i] = 0.f;

    float mr0 = -1e30f, mr1 = -1e30f;
    int qrow = q0 + wid * 16 + gid;
    const __nv_bfloat16* bptr0 = g_biasb + (size_t)qrow * TPAD + tig * 2;
    const __nv_bfloat16* bptr1 = bptr0 + 8 * TPAD;

    const unsigned b_ones[2] = {0x3C003C00u, 0x3C003C00u};   // fp16 (1,1)

    for (int kt = 0; kt < 64; kt++) {
        int k0 = kt * 64;
        float s[8][4];
        #pragma unroll
        for (int j = 0; j < 8; j++) {
            unsigned u0 = *(const unsigned*)(bptr0 + k0 + j * 8);
            unsigned u1 = *(const unsigned*)(bptr1 + k0 + j * 8);
            s[j][0] = __uint_as_float(u0 << 16);
            s[j][1] = __uint_as_float(u0 & 0xffff0000u);
            s[j][2] = __uint_as_float(u1 << 16);
            s[j][3] = __uint_as_float(u1 & 0xffff0000u);
        }

        if (kt == 63) cp_wait0(); else cp_wait1();
        __syncthreads();
        if (kt < 62) issue(kt + 2);
        int buf = kt % 3;
        const __nv_bfloat16* kd = Ks + buf * 64 * LPK;
        const __half*        vd = Vt + buf * 64 * LPK;

        #pragma unroll
        for (int ks = 0; ks < 4; ks++) {
            #pragma unroll
            for (int jp = 0; jp < 4; jp++) {
                unsigned kb[4];
                ldsm4(kb, kd + (jp * 16 + brow) * LPK + ks * 16 + bkhi * 8);
                mma16816(s[2 * jp],     qa[ks], &kb[0]);
                mma16816(s[2 * jp + 1], qa[ks], &kb[2]);
            }
        }

        float rm0 = -1e30f, rm1 = -1e30f;
        #pragma unroll
        for (int j = 0; j < 8; j++) {
            rm0 = fmaxf(rm0, fmaxf(s[j][0], s[j][1]));
            rm1 = fmaxf(rm1, fmaxf(s[j][2], s[j][3]));
        }
        rm0 = fmaxf(rm0, __shfl_xor_sync(0xffffffffu, rm0, 1));
        rm0 = fmaxf(rm0, __shfl_xor_sync(0xffffffffu, rm0, 2));
        rm1 = fmaxf(rm1, __shfl_xor_sync(0xffffffffu, rm1, 1));
        rm1 = fmaxf(rm1, __shfl_xor_sync(0xffffffffu, rm1, 2));
        float mn0 = fmaxf(mr0, rm0), mn1 = fmaxf(mr1, rm1);

        unsigned ph0[8], ph1[8];
        #pragma unroll
        for (int j = 0; j < 8; j++) {
            ph0[j] = ex2h2(cvt_f16x2(s[j][0] - mn0, s[j][1] - mn0));
            ph1[j] = ex2h2(cvt_f16x2(s[j][2] - mn1, s[j][3] - mn1));
        }

        if (__any_sync(0xffffffffu, (mn0 > mr0) | (mn1 > mr1))) {
            float al0 = ex2(mr0 - mn0), al1 = ex2(mr1 - mn1);
            #pragma unroll
            for (int j = 0; j < 8; j++) {
                oacc[j][0] *= al0; oacc[j][1] *= al0;
                oacc[j][2] *= al1; oacc[j][3] *= al1;
            }
            oacc_l[0] *= al0; oacc_l[1] *= al0;
            oacc_l[2] *= al1; oacc_l[3] *= al1;
        }
        mr0 = mn0; mr1 = mn1;

        #pragma unroll
        for (int kk = 0; kk < 4; kk++) {
            unsigned a[4];
            a[0] = ph0[2 * kk];
            a[1] = ph1[2 * kk];
            a[2] = ph0[2 * kk + 1];
            a[3] = ph1[2 * kk + 1];
            #pragma unroll
            for (int jp = 0; jp < 4; jp++) {
                unsigned vb[4];
                ldsm4(vb, vd + (jp * 16 + brow) * LPK + kk * 16 + bkhi * 8);
                mma16816h(oacc[2 * jp],     a, &vb[0]);
                mma16816h(oacc[2 * jp + 1], a, &vb[2]);
            }
            mma16816h(oacc_l, a, b_ones);
        }
    }

    float inv0 = 1.f / oacc_l[0], inv1 = 1.f / oacc_l[2];
    #pragma unroll
    for (int j = 0; j < 8; j++) {
        int col = head * DH + j * 8 + tig * 2;
        __nv_bfloat16* d0 = g_att + (size_t)qrow * NS + col;
        __nv_bfloat16* d1 = g_att + (size_t)(qrow + 8) * NS + col;
        d0[0] = __float2bfloat16(oacc[j][0] * inv0);
        d0[1] = __float2bfloat16(oacc[j][1] * inv0);
        d1[0] = __float2bfloat16(oacc[j][2] * inv1);
        d1[1] = __float2bfloat16(oacc[j][3] * inv1);
    }
}

// ---------------- launch ----------------
extern "C" void kernel_launch(void* const* d_in, const int* in_sizes, int n_in,
                              void* d_out, int out_size) {
    const float* m     = (const float*)d_in[0];
    const float* bias  = (const float*)d_in[1];
    const float* gamma = (const float*)d_in[2];
    const float* beta  = (const float*)d_in[3];
    const float* Wq    = (const float*)d_in[4];
    const float* bq    = (const float*)d_in[5];
    const float* Wk    = (const float*)d_in[6];
    const float* Wv    = (const float*)d_in[7];
    const float* bv    = (const float*)d_in[8];
    const float* Wc    = (const float*)d_in[9];
    const float* bc    = (const float*)d_in[10];
    float* out = (float*)d_out;

    prolog_kernel<<<8192, 256>>>(m, gamma, beta, Wq, Wk, Wv, Wc);

    gemm_qkv_kernel<<<dim3(32, 32), 256>>>(bq, bv, bias);

    cudaFuncSetAttribute(attn_kernel, cudaFuncAttributeMaxDynamicSharedMemorySize, ATTN_SMEM);
    attn_kernel<<<dim3(NH, TPAD / 128), 256, ATTN_SMEM>>>();

    gemm_out_kernel<<<dim3(8, 32), 256>>>(bc, m, out);
}